// round 1
// baseline (speedup 1.0000x reference)
#include <cuda_runtime.h>
#include <math.h>

// Problem dims (fixed)
#define Bb  2
#define Ll  2048
#define Dd  1024
#define Hh  16
#define HDd 64
#define LH  8          // local (causal) heads

// Scratch: Q,K,V,O in [B, L, H, HD] layout (== [B*L, D] row-major)
__device__ float g_Q[Bb * Ll * Dd];
__device__ float g_K[Bb * Ll * Dd];
__device__ float g_V[Bb * Ll * Dd];
__device__ float g_O[Bb * Ll * Dd];

// ---------------------------------------------------------------------------
// sgemm + bias: C[M,N] = A[M,K] @ W[K,N] + bias,  M=4096, N=1024, K=1024
// 128x128 tile, BK=8, 256 threads, 8x8 per-thread microtile
// ---------------------------------------------------------------------------
__global__ __launch_bounds__(256) void sgemm_bias(
    const float* __restrict__ A, const float* __restrict__ W,
    const float* __restrict__ bias, float* __restrict__ C)
{
    const int M = 4096, N = 1024, K = 1024;
    (void)M;
    __shared__ float As[8][128];
    __shared__ float Bs[8][128];

    int tid = threadIdx.x;
    int rowBase = blockIdx.y * 128;
    int colBase = blockIdx.x * 128;

    int trow = (tid >> 4) * 8;   // 0..120
    int tcol = (tid & 15) * 8;   // 0..120

    int arow = tid >> 1;           // 0..127
    int acol = (tid & 1) * 4;      // 0 or 4
    int brow = tid >> 5;           // 0..7
    int bcol = (tid & 31) * 4;     // 0..124

    float acc[8][8];
    #pragma unroll
    for (int m = 0; m < 8; m++)
        #pragma unroll
        for (int n = 0; n < 8; n++) acc[m][n] = 0.f;

    for (int k0 = 0; k0 < K; k0 += 8) {
        float4 av = *(const float4*)&A[(size_t)(rowBase + arow) * K + k0 + acol];
        As[acol + 0][arow] = av.x;
        As[acol + 1][arow] = av.y;
        As[acol + 2][arow] = av.z;
        As[acol + 3][arow] = av.w;
        *(float4*)&Bs[brow][bcol] =
            *(const float4*)&W[(size_t)(k0 + brow) * N + colBase + bcol];
        __syncthreads();

        #pragma unroll
        for (int kk = 0; kk < 8; kk++) {
            float a[8], b[8];
            *(float4*)(a)     = *(float4*)&As[kk][trow];
            *(float4*)(a + 4) = *(float4*)&As[kk][trow + 4];
            *(float4*)(b)     = *(float4*)&Bs[kk][tcol];
            *(float4*)(b + 4) = *(float4*)&Bs[kk][tcol + 4];
            #pragma unroll
            for (int m = 0; m < 8; m++)
                #pragma unroll
                for (int n = 0; n < 8; n++)
                    acc[m][n] = fmaf(a[m], b[n], acc[m][n]);
        }
        __syncthreads();
    }

    #pragma unroll
    for (int m = 0; m < 8; m++) {
        size_t base = (size_t)(rowBase + trow + m) * N + colBase + tcol;
        #pragma unroll
        for (int n = 0; n < 8; n += 4) {
            float4 v;
            v.x = acc[m][n + 0] + bias[colBase + tcol + n + 0];
            v.y = acc[m][n + 1] + bias[colBase + tcol + n + 1];
            v.z = acc[m][n + 2] + bias[colBase + tcol + n + 2];
            v.w = acc[m][n + 3] + bias[colBase + tcol + n + 3];
            *(float4*)&C[base + n] = v;
        }
    }
}

// ---------------------------------------------------------------------------
// Scores: S[b,h] = Q[b,h] @ K[b,h]^T * (inv_sqrt * scale)  -> attn buffers
// Batched GEMM: M=N=2048, K=64. 128x128 tile, BK=8, 8x8 microtile.
// Fully-masked causal blocks are skipped (softmax writes zeros there).
// ---------------------------------------------------------------------------
__global__ __launch_bounds__(256) void scores_kernel(
    const float* __restrict__ sc_local, const float* __restrict__ sc_global,
    float* __restrict__ attnL, float* __restrict__ attnG)
{
    int bh = blockIdx.z;
    int b = bh >> 4, h = bh & 15;
    int rowBase = blockIdx.y * 128;
    int colBase = blockIdx.x * 128;
    bool is_local = (h < LH);
    if (is_local && colBase > rowBase + 127) return;  // fully above diagonal

    const float* Qb = g_Q + (size_t)b * Ll * Dd + h * HDd;
    const float* Kb = g_K + (size_t)b * Ll * Dd + h * HDd;
    float scale = rsqrtf((float)HDd) * (is_local ? sc_local[0] : sc_global[0]);
    float* dst = is_local ? attnL + (size_t)(b * LH + h) * Ll * Ll
                          : attnG + (size_t)(b * LH + h - LH) * Ll * Ll;

    __shared__ float As[8][128];
    __shared__ float Bs[8][128];

    int tid  = threadIdx.x;
    int trow = (tid >> 4) * 8;
    int tcol = (tid & 15) * 8;
    int lrow = tid >> 1;           // 0..127
    int lcol = (tid & 1) * 4;      // 0 or 4

    float acc[8][8];
    #pragma unroll
    for (int m = 0; m < 8; m++)
        #pragma unroll
        for (int n = 0; n < 8; n++) acc[m][n] = 0.f;

    for (int k0 = 0; k0 < HDd; k0 += 8) {
        float4 av = *(const float4*)&Qb[(size_t)(rowBase + lrow) * Dd + k0 + lcol];
        As[lcol + 0][lrow] = av.x;
        As[lcol + 1][lrow] = av.y;
        As[lcol + 2][lrow] = av.z;
        As[lcol + 3][lrow] = av.w;
        float4 bv = *(const float4*)&Kb[(size_t)(colBase + lrow) * Dd + k0 + lcol];
        Bs[lcol + 0][lrow] = bv.x;
        Bs[lcol + 1][lrow] = bv.y;
        Bs[lcol + 2][lrow] = bv.z;
        Bs[lcol + 3][lrow] = bv.w;
        __syncthreads();

        #pragma unroll
        for (int kk = 0; kk < 8; kk++) {
            float a[8], bb[8];
            *(float4*)(a)      = *(float4*)&As[kk][trow];
            *(float4*)(a + 4)  = *(float4*)&As[kk][trow + 4];
            *(float4*)(bb)     = *(float4*)&Bs[kk][tcol];
            *(float4*)(bb + 4) = *(float4*)&Bs[kk][tcol + 4];
            #pragma unroll
            for (int m = 0; m < 8; m++)
                #pragma unroll
                for (int n = 0; n < 8; n++)
                    acc[m][n] = fmaf(a[m], bb[n], acc[m][n]);
        }
        __syncthreads();
    }

    #pragma unroll
    for (int m = 0; m < 8; m++) {
        size_t base = (size_t)(rowBase + trow + m) * Ll + colBase + tcol;
        #pragma unroll
        for (int n = 0; n < 8; n += 4) {
            float4 v;
            v.x = acc[m][n + 0] * scale;
            v.y = acc[m][n + 1] * scale;
            v.z = acc[m][n + 2] * scale;
            v.w = acc[m][n + 3] * scale;
            *(float4*)&dst[base + n] = v;
        }
    }
}

// ---------------------------------------------------------------------------
// Softmax per row, in place. Local heads: masked positions -> exact 0.
// One block (256 threads) per row; row of 2048 held in 8 regs/thread.
// ---------------------------------------------------------------------------
__global__ __launch_bounds__(256) void softmax_kernel(
    float* __restrict__ attnL, float* __restrict__ attnG)
{
    int q  = blockIdx.x;
    int bh = blockIdx.y;
    int b = bh >> 4, h = bh & 15;
    bool is_local = (h < LH);
    float* row = (is_local ? attnL + (size_t)(b * LH + h) * Ll * Ll
                           : attnG + (size_t)(b * LH + h - LH) * Ll * Ll)
                 + (size_t)q * Ll;
    int n = is_local ? q + 1 : Ll;

    int tid = threadIdx.x;
    __shared__ float smax[8];
    __shared__ float ssum[8];

    float vals[8];
    float mx = -INFINITY;
    #pragma unroll
    for (int j = 0; j < 8; j++) {
        int i = tid + j * 256;
        vals[j] = (i < n) ? row[i] : -INFINITY;
        mx = fmaxf(mx, vals[j]);
    }
    #pragma unroll
    for (int o = 16; o; o >>= 1) mx = fmaxf(mx, __shfl_xor_sync(0xffffffffu, mx, o));
    if ((tid & 31) == 0) smax[tid >> 5] = mx;
    __syncthreads();
    mx = fmaxf(fmaxf(fmaxf(smax[0], smax[1]), fmaxf(smax[2], smax[3])),
               fmaxf(fmaxf(smax[4], smax[5]), fmaxf(smax[6], smax[7])));

    float s = 0.f;
    #pragma unroll
    for (int j = 0; j < 8; j++) {
        int i = tid + j * 256;
        vals[j] = (i < n) ? __expf(vals[j] - mx) : 0.f;
        s += vals[j];
    }
    #pragma unroll
    for (int o = 16; o; o >>= 1) s += __shfl_xor_sync(0xffffffffu, s, o);
    if ((tid & 31) == 0) ssum[tid >> 5] = s;
    __syncthreads();
    s = (ssum[0] + ssum[1]) + (ssum[2] + ssum[3]) +
        (ssum[4] + ssum[5]) + (ssum[6] + ssum[7]);
    float inv = 1.f / s;

    #pragma unroll
    for (int j = 0; j < 8; j++) {
        int i = tid + j * 256;
        row[i] = vals[j] * inv;   // masked positions hold 0 -> write exact 0
    }
}

// ---------------------------------------------------------------------------
// O[b,h] = P[b,h] @ V[b,h]:  M=2048, N=64, K=2048 (truncated at diagonal for
// local heads). 128x64 tile, BK=16, 8x4 microtile, 256 threads.
// ---------------------------------------------------------------------------
__global__ __launch_bounds__(256) void av_kernel(
    const float* __restrict__ attnL, const float* __restrict__ attnG)
{
    int bh = blockIdx.z;
    int b = bh >> 4, h = bh & 15;
    int rowBase = blockIdx.y * 128;
    bool is_local = (h < LH);

    const float* P = (is_local ? attnL + (size_t)(b * LH + h) * Ll * Ll
                               : attnG + (size_t)(b * LH + h - LH) * Ll * Ll);
    const float* Vb = g_V + (size_t)b * Ll * Dd + h * HDd;
    float* Ob       = g_O + (size_t)b * Ll * Dd + h * HDd;

    int kmax = is_local ? (rowBase + 128) : Ll;

    __shared__ float As[16][128];
    __shared__ float Bs[16][64];

    int tid  = threadIdx.x;
    int trow = (tid >> 4) * 8;   // 0..120
    int tcol = (tid & 15) * 4;   // 0..60

    float acc[8][4];
    #pragma unroll
    for (int m = 0; m < 8; m++)
        #pragma unroll
        for (int n = 0; n < 4; n++) acc[m][n] = 0.f;

    int bk = tid >> 4;           // 0..15
    int bn = (tid & 15) * 4;     // 0..60

    for (int k0 = 0; k0 < kmax; k0 += 16) {
        #pragma unroll
        for (int j = 0; j < 2; j++) {
            int i = tid + j * 256;     // 0..511
            int m = i >> 2;            // 0..127
            int kc = (i & 3) * 4;      // 0,4,8,12
            float4 v = *(const float4*)&P[(size_t)(rowBase + m) * Ll + k0 + kc];
            As[kc + 0][m] = v.x;
            As[kc + 1][m] = v.y;
            As[kc + 2][m] = v.z;
            As[kc + 3][m] = v.w;
        }
        *(float4*)&Bs[bk][bn] = *(const float4*)&Vb[(size_t)(k0 + bk) * Dd + bn];
        __syncthreads();

        #pragma unroll
        for (int kk = 0; kk < 16; kk++) {
            float a[8], bv[4];
            *(float4*)(a)     = *(float4*)&As[kk][trow];
            *(float4*)(a + 4) = *(float4*)&As[kk][trow + 4];
            *(float4*)(bv)    = *(float4*)&Bs[kk][tcol];
            #pragma unroll
            for (int m = 0; m < 8; m++)
                #pragma unroll
                for (int n = 0; n < 4; n++)
                    acc[m][n] = fmaf(a[m], bv[n], acc[m][n]);
        }
        __syncthreads();
    }

    #pragma unroll
    for (int m = 0; m < 8; m++) {
        float4 v;
        v.x = acc[m][0]; v.y = acc[m][1]; v.z = acc[m][2]; v.w = acc[m][3];
        *(float4*)&Ob[(size_t)(rowBase + trow + m) * Dd + tcol] = v;
    }
}

// ---------------------------------------------------------------------------
extern "C" void kernel_launch(void* const* d_in, const int* in_sizes, int n_in,
                              void* d_out, int out_size)
{
    const float* x   = (const float*)d_in[0];
    const float* Wq  = (const float*)d_in[1];
    const float* bq  = (const float*)d_in[2];
    const float* Wk  = (const float*)d_in[3];
    const float* bk  = (const float*)d_in[4];
    const float* Wv  = (const float*)d_in[5];
    const float* bv  = (const float*)d_in[6];
    const float* Wo  = (const float*)d_in[7];
    const float* bo  = (const float*)d_in[8];
    const float* lsc = (const float*)d_in[9];
    const float* gsc = (const float*)d_in[10];

    float* out   = (float*)d_out;
    float* attnL = out + (size_t)Bb * Ll * Dd;
    float* attnG = attnL + (size_t)Bb * LH * Ll * Ll;

    float *gq, *gk, *gv, *go;
    cudaGetSymbolAddress((void**)&gq, g_Q);
    cudaGetSymbolAddress((void**)&gk, g_K);
    cudaGetSymbolAddress((void**)&gv, g_V);
    cudaGetSymbolAddress((void**)&go, g_O);

    dim3 pg(1024 / 128, 4096 / 128);           // (8, 32)
    sgemm_bias<<<pg, 256>>>(x, Wq, bq, gq);
    sgemm_bias<<<pg, 256>>>(x, Wk, bk, gk);
    sgemm_bias<<<pg, 256>>>(x, Wv, bv, gv);

    scores_kernel<<<dim3(16, 16, 32), 256>>>(lsc, gsc, attnL, attnG);
    softmax_kernel<<<dim3(Ll, 32), 256>>>(attnL, attnG);
    av_kernel<<<dim3(1, 16, 32), 256>>>(attnL, attnG);

    sgemm_bias<<<pg, 256>>>(go, Wo, bo, out);
}

// round 2
// speedup vs baseline: 1.9261x; 1.9261x over previous
#include <cuda_runtime.h>
#include <cuda_bf16.h>
#include <math.h>
#include <stdint.h>

#define Bb 2
#define Ll 2048
#define Dd 1024
#define LH 8
#define MLEN (Bb * Ll)   // 4096

// ---------------- scratch (bf16 hi/lo pairs, stored as uint16) ----------------
__device__ uint16_t g_xh[MLEN * Dd], g_xl[MLEN * Dd];
__device__ uint16_t g_Wqh[Dd * Dd], g_Wql[Dd * Dd];
__device__ uint16_t g_Wkh[Dd * Dd], g_Wkl[Dd * Dd];
__device__ uint16_t g_Wvh[Dd * Dd], g_Wvl[Dd * Dd];
__device__ uint16_t g_Woh[Dd * Dd], g_Wol[Dd * Dd];
__device__ uint16_t g_Qh[MLEN * Dd], g_Ql[MLEN * Dd];
__device__ uint16_t g_Kh[MLEN * Dd], g_Kl[MLEN * Dd];
__device__ uint16_t g_Vh[MLEN * Dd], g_Vl[MLEN * Dd];
__device__ uint16_t g_Oh[MLEN * Dd], g_Ol[MLEN * Dd];

// ---------------- helpers ----------------
__device__ __forceinline__ uint32_t smem_u32(const void* p) {
    return (uint32_t)__cvta_generic_to_shared(p);
}

// split two floats -> packed bf16x2 hi (truncation) + bf16x2 lo (rn of residual)
__device__ __forceinline__ void pack_split2(float x0, float x1, uint32_t& h, uint32_t& l) {
    uint32_t u0 = __float_as_uint(x0), u1 = __float_as_uint(x1);
    h = (u0 >> 16) | (u1 & 0xffff0000u);
    float r0 = x0 - __uint_as_float(u0 & 0xffff0000u);
    float r1 = x1 - __uint_as_float(u1 & 0xffff0000u);
    asm("cvt.rn.bf16x2.f32 %0, %1, %2;" : "=r"(l) : "f"(r1), "f"(r0));
}

__device__ __forceinline__ void split_f4(float4 v, uint2& h, uint2& l) {
    pack_split2(v.x, v.y, h.x, l.x);
    pack_split2(v.z, v.w, h.y, l.y);
}

__device__ __forceinline__ void ldsm_x4(uint32_t addr, uint32_t& r0, uint32_t& r1,
                                        uint32_t& r2, uint32_t& r3) {
    asm volatile("ldmatrix.sync.aligned.m8n8.x4.shared.b16 {%0,%1,%2,%3}, [%4];"
                 : "=r"(r0), "=r"(r1), "=r"(r2), "=r"(r3) : "r"(addr));
}
__device__ __forceinline__ void ldsm_x4_t(uint32_t addr, uint32_t& r0, uint32_t& r1,
                                          uint32_t& r2, uint32_t& r3) {
    asm volatile("ldmatrix.sync.aligned.m8n8.x4.trans.shared.b16 {%0,%1,%2,%3}, [%4];"
                 : "=r"(r0), "=r"(r1), "=r"(r2), "=r"(r3) : "r"(addr));
}

__device__ __forceinline__ void mma_bf16(float* c, const uint32_t* a,
                                         uint32_t b0, uint32_t b1) {
    asm volatile(
        "mma.sync.aligned.m16n8k16.row.col.f32.bf16.bf16.f32 "
        "{%0,%1,%2,%3},{%4,%5,%6,%7},{%8,%9},{%0,%1,%2,%3};"
        : "+f"(c[0]), "+f"(c[1]), "+f"(c[2]), "+f"(c[3])
        : "r"(a[0]), "r"(a[1]), "r"(a[2]), "r"(a[3]), "r"(b0), "r"(b1));
}

// ---------------- pre-split f32 -> bf16 hi/lo ----------------
__global__ void split_kernel(const float4* __restrict__ src, uint2* __restrict__ h,
                             uint2* __restrict__ l, int n4) {
    int i = blockIdx.x * 256 + threadIdx.x;
    if (i < n4) {
        uint2 hh, ll;
        split_f4(src[i], hh, ll);
        h[i] = hh;
        l[i] = ll;
    }
}

// ---------------- projection GEMM ----------------
// C[4096,1024] = A[4096,1024] @ W[1024,1024] + bias (A,W given as bf16 hi/lo)
// block tile 128x256, 8 warps (2x4), warp tile 64x64, kstep 16
// mode 1: write bf16 hi/lo split; mode 0: write f32
#define PA 24
#define PBT 264
__global__ __launch_bounds__(256) void gemm_proj(
    const uint16_t* __restrict__ Ah, const uint16_t* __restrict__ Al,
    const uint16_t* __restrict__ Bh, const uint16_t* __restrict__ Bl,
    const float* __restrict__ bias,
    uint16_t* __restrict__ outH, uint16_t* __restrict__ outL,
    float* __restrict__ outF, int mode)
{
    const int N = 1024, K = 1024;
    __shared__ __align__(16) uint16_t Ash[128 * PA], Asl[128 * PA];
    __shared__ __align__(16) uint16_t Bsh[16 * PBT], Bsl[16 * PBT];

    int tid = threadIdx.x, lane = tid & 31, wid = tid >> 5;
    int rowBase = blockIdx.y * 128, colBase = blockIdx.x * 256;
    int m0 = (wid >> 2) * 64, n0 = (wid & 3) * 64;

    // staging indices
    int ar = tid >> 1, asel = (tid & 1) * 8;
    int bk = tid >> 5, bs = (tid & 31) * 8;

    float c[4][8][4];
    #pragma unroll
    for (int i = 0; i < 4; i++)
        #pragma unroll
        for (int j = 0; j < 8; j++)
            #pragma unroll
            for (int q = 0; q < 4; q++) c[i][j][q] = 0.f;

    uint32_t sAh = smem_u32(Ash), sAl = smem_u32(Asl);
    uint32_t sBh = smem_u32(Bsh), sBl = smem_u32(Bsl);
    uint32_t aoff = (((m0 + (lane & 15)) * PA) + (lane >> 4) * 8) * 2;
    uint32_t boff = ((((lane & 7) + ((lane >> 3) & 1) * 8) * PBT) +
                     n0 + (lane >> 4) * 8) * 2;

    size_t aRow = (size_t)(rowBase + ar) * K;

    uint4 rah, ral, rbh0, rbh1, rbl0, rbl1;
    rah  = *(const uint4*)&Ah[aRow + asel];
    ral  = *(const uint4*)&Al[aRow + asel];
    rbh0 = *(const uint4*)&Bh[(size_t)bk * N + colBase + bs];
    rbh1 = *(const uint4*)&Bh[(size_t)(bk + 8) * N + colBase + bs];
    rbl0 = *(const uint4*)&Bl[(size_t)bk * N + colBase + bs];
    rbl1 = *(const uint4*)&Bl[(size_t)(bk + 8) * N + colBase + bs];

    const int NK = K / 16;
    for (int ks = 0; ks < NK; ks++) {
        *(uint4*)&Ash[ar * PA + asel] = rah;
        *(uint4*)&Asl[ar * PA + asel] = ral;
        *(uint4*)&Bsh[bk * PBT + bs] = rbh0;
        *(uint4*)&Bsh[(bk + 8) * PBT + bs] = rbh1;
        *(uint4*)&Bsl[bk * PBT + bs] = rbl0;
        *(uint4*)&Bsl[(bk + 8) * PBT + bs] = rbl1;
        __syncthreads();

        if (ks + 1 < NK) {
            int k0 = (ks + 1) * 16;
            rah  = *(const uint4*)&Ah[aRow + k0 + asel];
            ral  = *(const uint4*)&Al[aRow + k0 + asel];
            rbh0 = *(const uint4*)&Bh[(size_t)(k0 + bk) * N + colBase + bs];
            rbh1 = *(const uint4*)&Bh[(size_t)(k0 + bk + 8) * N + colBase + bs];
            rbl0 = *(const uint4*)&Bl[(size_t)(k0 + bk) * N + colBase + bs];
            rbl1 = *(const uint4*)&Bl[(size_t)(k0 + bk + 8) * N + colBase + bs];
        }

        uint32_t afh[4][4], afl[4][4];
        #pragma unroll
        for (int i = 0; i < 4; i++) {
            ldsm_x4(sAh + aoff + i * 768, afh[i][0], afh[i][1], afh[i][2], afh[i][3]);
            ldsm_x4(sAl + aoff + i * 768, afl[i][0], afl[i][1], afl[i][2], afl[i][3]);
        }
        #pragma unroll
        for (int j = 0; j < 4; j++) {
            uint32_t bh0, bh1, bh2, bh3, bl0, bl1, bl2, bl3;
            ldsm_x4_t(sBh + boff + j * 32, bh0, bh1, bh2, bh3);
            ldsm_x4_t(sBl + boff + j * 32, bl0, bl1, bl2, bl3);
            #pragma unroll
            for (int i = 0; i < 4; i++) {
                mma_bf16(c[i][2 * j], afh[i], bh0, bh1);
                mma_bf16(c[i][2 * j], afh[i], bl0, bl1);
                mma_bf16(c[i][2 * j], afl[i], bh0, bh1);
                mma_bf16(c[i][2 * j + 1], afh[i], bh2, bh3);
                mma_bf16(c[i][2 * j + 1], afh[i], bl2, bl3);
                mma_bf16(c[i][2 * j + 1], afl[i], bh2, bh3);
            }
        }
        __syncthreads();
    }

    // epilogue
    int r = lane >> 2, cl2 = (lane & 3) * 2;
    #pragma unroll
    for (int i = 0; i < 4; i++) {
        int row = rowBase + m0 + i * 16 + r;
        #pragma unroll
        for (int j = 0; j < 8; j++) {
            int col = colBase + n0 + j * 8 + cl2;
            float b0 = bias[col], b1 = bias[col + 1];
            float x0 = c[i][j][0] + b0, x1 = c[i][j][1] + b1;
            float y0 = c[i][j][2] + b0, y1 = c[i][j][3] + b1;
            if (mode) {
                uint32_t hh, ll;
                pack_split2(x0, x1, hh, ll);
                *(uint32_t*)&outH[(size_t)row * N + col] = hh;
                *(uint32_t*)&outL[(size_t)row * N + col] = ll;
                pack_split2(y0, y1, hh, ll);
                *(uint32_t*)&outH[(size_t)(row + 8) * N + col] = hh;
                *(uint32_t*)&outL[(size_t)(row + 8) * N + col] = ll;
            } else {
                *(float2*)&outF[(size_t)row * N + col] = make_float2(x0, x1);
                *(float2*)&outF[(size_t)(row + 8) * N + col] = make_float2(y0, y1);
            }
        }
    }
}

// ---------------- scores: S = Q @ K^T * scale ----------------
// per (b,h): M=N=2048, K=64. block 128x256, warp 64x64.
__global__ __launch_bounds__(256) void scores_mma(
    const uint16_t* __restrict__ Qh, const uint16_t* __restrict__ Ql,
    const uint16_t* __restrict__ Kh, const uint16_t* __restrict__ Kl,
    const float* __restrict__ lsc, const float* __restrict__ gsc,
    float* __restrict__ attnL, float* __restrict__ attnG)
{
    int bh = blockIdx.z;
    int b = bh >> 4, h = bh & 15;
    int rowBase = blockIdx.y * 128, colBase = blockIdx.x * 256;
    bool is_local = (h < LH);
    if (is_local && colBase > rowBase + 127) return;

    float scale = 0.125f * (is_local ? lsc[0] : gsc[0]);
    float* dst = is_local ? attnL + (size_t)(b * LH + h) * Ll * Ll
                          : attnG + (size_t)(b * LH + h - LH) * Ll * Ll;

    __shared__ __align__(16) uint16_t Ash[128 * PA], Asl[128 * PA];
    __shared__ __align__(16) uint16_t Bsh[256 * PA], Bsl[256 * PA];

    int tid = threadIdx.x, lane = tid & 31, wid = tid >> 5;
    int m0 = (wid >> 2) * 64, n0 = (wid & 3) * 64;

    int ar = tid >> 1, asel = (tid & 1) * 8;   // A: 128 rows x 16
    // B: 256 rows x 16; two loads per thread (rows ar, ar+128)
    size_t aRow = (size_t)(b * Ll + rowBase + ar) * Dd + h * 64;
    size_t bRow0 = (size_t)(b * Ll + colBase + ar) * Dd + h * 64;
    size_t bRow1 = (size_t)(b * Ll + colBase + ar + 128) * Dd + h * 64;

    float c[4][8][4];
    #pragma unroll
    for (int i = 0; i < 4; i++)
        #pragma unroll
        for (int j = 0; j < 8; j++)
            #pragma unroll
            for (int q = 0; q < 4; q++) c[i][j][q] = 0.f;

    uint32_t sAh = smem_u32(Ash), sAl = smem_u32(Asl);
    uint32_t sBh = smem_u32(Bsh), sBl = smem_u32(Bsl);
    uint32_t aoff = (((m0 + (lane & 15)) * PA) + (lane >> 4) * 8) * 2;
    uint32_t boff = (((n0 + (lane & 7) + (lane >> 4) * 8) * PA) +
                     ((lane >> 3) & 1) * 8) * 2;

    uint4 rah, ral, rbh0, rbh1, rbl0, rbl1;
    rah  = *(const uint4*)&Qh[aRow + asel];
    ral  = *(const uint4*)&Ql[aRow + asel];
    rbh0 = *(const uint4*)&Kh[bRow0 + asel];
    rbh1 = *(const uint4*)&Kh[bRow1 + asel];
    rbl0 = *(const uint4*)&Kl[bRow0 + asel];
    rbl1 = *(const uint4*)&Kl[bRow1 + asel];

    const int NK = 4;   // K = 64
    for (int ks = 0; ks < NK; ks++) {
        *(uint4*)&Ash[ar * PA + asel] = rah;
        *(uint4*)&Asl[ar * PA + asel] = ral;
        *(uint4*)&Bsh[ar * PA + asel] = rbh0;
        *(uint4*)&Bsh[(ar + 128) * PA + asel] = rbh1;
        *(uint4*)&Bsl[ar * PA + asel] = rbl0;
        *(uint4*)&Bsl[(ar + 128) * PA + asel] = rbl1;
        __syncthreads();

        if (ks + 1 < NK) {
            int k0 = (ks + 1) * 16;
            rah  = *(const uint4*)&Qh[aRow + k0 + asel];
            ral  = *(const uint4*)&Ql[aRow + k0 + asel];
            rbh0 = *(const uint4*)&Kh[bRow0 + k0 + asel];
            rbh1 = *(const uint4*)&Kh[bRow1 + k0 + asel];
            rbl0 = *(const uint4*)&Kl[bRow0 + k0 + asel];
            rbl1 = *(const uint4*)&Kl[bRow1 + k0 + asel];
        }

        uint32_t afh[4][4], afl[4][4];
        #pragma unroll
        for (int i = 0; i < 4; i++) {
            ldsm_x4(sAh + aoff + i * 768, afh[i][0], afh[i][1], afh[i][2], afh[i][3]);
            ldsm_x4(sAl + aoff + i * 768, afl[i][0], afl[i][1], afl[i][2], afl[i][3]);
        }
        #pragma unroll
        for (int j = 0; j < 4; j++) {
            uint32_t bh0, bh1, bh2, bh3, bl0, bl1, bl2, bl3;
            ldsm_x4(sBh + boff + j * 768, bh0, bh1, bh2, bh3);
            ldsm_x4(sBl + boff + j * 768, bl0, bl1, bl2, bl3);
            #pragma unroll
            for (int i = 0; i < 4; i++) {
                mma_bf16(c[i][2 * j], afh[i], bh0, bh1);
                mma_bf16(c[i][2 * j], afh[i], bl0, bl1);
                mma_bf16(c[i][2 * j], afl[i], bh0, bh1);
                mma_bf16(c[i][2 * j + 1], afh[i], bh2, bh3);
                mma_bf16(c[i][2 * j + 1], afh[i], bl2, bl3);
                mma_bf16(c[i][2 * j + 1], afl[i], bh2, bh3);
            }
        }
        __syncthreads();
    }

    int r = lane >> 2, cl2 = (lane & 3) * 2;
    #pragma unroll
    for (int i = 0; i < 4; i++) {
        int row = rowBase + m0 + i * 16 + r;
        #pragma unroll
        for (int j = 0; j < 8; j++) {
            size_t off = (size_t)row * Ll + colBase + n0 + j * 8 + cl2;
            *(float2*)&dst[off] =
                make_float2(c[i][j][0] * scale, c[i][j][1] * scale);
            *(float2*)&dst[off + 8 * Ll] =
                make_float2(c[i][j][2] * scale, c[i][j][3] * scale);
        }
    }
}

// ---------------- softmax (rowwise, in place; exact zeros in mask) ----------------
__global__ __launch_bounds__(256) void softmax_kernel(
    float* __restrict__ attnL, float* __restrict__ attnG)
{
    int q = blockIdx.x;
    int bh = blockIdx.y;
    int b = bh >> 4, h = bh & 15;
    bool is_local = (h < LH);
    float* row = (is_local ? attnL + (size_t)(b * LH + h) * Ll * Ll
                           : attnG + (size_t)(b * LH + h - LH) * Ll * Ll)
                 + (size_t)q * Ll;
    int n = is_local ? q + 1 : Ll;

    int tid = threadIdx.x;
    __shared__ float smax[8];
    __shared__ float ssum[8];

    float vals[8];
    float mx = -INFINITY;
    #pragma unroll
    for (int j = 0; j < 8; j++) {
        int i = tid + j * 256;
        vals[j] = (i < n) ? row[i] : -INFINITY;
        mx = fmaxf(mx, vals[j]);
    }
    #pragma unroll
    for (int o = 16; o; o >>= 1) mx = fmaxf(mx, __shfl_xor_sync(0xffffffffu, mx, o));
    if ((tid & 31) == 0) smax[tid >> 5] = mx;
    __syncthreads();
    mx = fmaxf(fmaxf(fmaxf(smax[0], smax[1]), fmaxf(smax[2], smax[3])),
               fmaxf(fmaxf(smax[4], smax[5]), fmaxf(smax[6], smax[7])));

    float s = 0.f;
    #pragma unroll
    for (int j = 0; j < 8; j++) {
        int i = tid + j * 256;
        vals[j] = (i < n) ? __expf(vals[j] - mx) : 0.f;
        s += vals[j];
    }
    #pragma unroll
    for (int o = 16; o; o >>= 1) s += __shfl_xor_sync(0xffffffffu, s, o);
    if ((tid & 31) == 0) ssum[tid >> 5] = s;
    __syncthreads();
    s = (ssum[0] + ssum[1]) + (ssum[2] + ssum[3]) +
        (ssum[4] + ssum[5]) + (ssum[6] + ssum[7]);
    float inv = 1.f / s;

    #pragma unroll
    for (int j = 0; j < 8; j++) {
        int i = tid + j * 256;
        row[i] = vals[j] * inv;
    }
}

// ---------------- AV: O = P @ V ----------------
// per (b,h): M=2048, N=64, K up to 2048. block 128x64, 8 warps, warp 32x32.
#define PBV 72
__global__ __launch_bounds__(256) void av_mma(
    const float* __restrict__ attnL, const float* __restrict__ attnG,
    const uint16_t* __restrict__ Vh, const uint16_t* __restrict__ Vl,
    uint16_t* __restrict__ Oh, uint16_t* __restrict__ Ol)
{
    int bh = blockIdx.y;
    int b = bh >> 4, h = bh & 15;
    int rowBase = blockIdx.x * 128;
    bool is_local = (h < LH);

    const float* P = is_local ? attnL + (size_t)(b * LH + h) * Ll * Ll
                              : attnG + (size_t)(b * LH + h - LH) * Ll * Ll;
    int kmax = is_local ? (rowBase + 128) : Ll;
    const int NK = kmax / 16;

    __shared__ __align__(16) uint16_t Ash[128 * PA], Asl[128 * PA];
    __shared__ __align__(16) uint16_t Bsh[16 * PBV], Bsl[16 * PBV];

    int tid = threadIdx.x, lane = tid & 31, wid = tid >> 5;
    int m0 = (wid >> 1) * 32, n0 = (wid & 1) * 32;

    int ar = tid >> 1, asel = (tid & 1) * 8;     // A: 128 x 16 f32 (2 float4 each)
    int vk = tid & 15, vseg = tid >> 4;          // B: 16 x 64 halves, uint2 each

    size_t aRow = (size_t)(rowBase + ar) * Ll;
    size_t vBase = (size_t)(b * Ll) * Dd + h * 64 + vseg * 4;

    float c[2][4][4];
    #pragma unroll
    for (int i = 0; i < 2; i++)
        #pragma unroll
        for (int j = 0; j < 4; j++)
            #pragma unroll
            for (int q = 0; q < 4; q++) c[i][j][q] = 0.f;

    uint32_t sAh = smem_u32(Ash), sAl = smem_u32(Asl);
    uint32_t sBh = smem_u32(Bsh), sBl = smem_u32(Bsl);
    uint32_t aoff = (((m0 + (lane & 15)) * PA) + (lane >> 4) * 8) * 2;
    uint32_t boff = ((((lane & 7) + ((lane >> 3) & 1) * 8) * PBV) +
                     n0 + (lane >> 4) * 8) * 2;

    float4 ra0, ra1;
    uint2 rbh, rbl;
    ra0 = *(const float4*)&P[aRow + asel];
    ra1 = *(const float4*)&P[aRow + asel + 4];
    rbh = *(const uint2*)&Vh[vBase + (size_t)vk * Dd];
    rbl = *(const uint2*)&Vl[vBase + (size_t)vk * Dd];

    for (int ks = 0; ks < NK; ks++) {
        uint2 h0, l0, h1, l1;
        split_f4(ra0, h0, l0);
        split_f4(ra1, h1, l1);
        *(uint2*)&Ash[ar * PA + asel] = h0;
        *(uint2*)&Ash[ar * PA + asel + 4] = h1;
        *(uint2*)&Asl[ar * PA + asel] = l0;
        *(uint2*)&Asl[ar * PA + asel + 4] = l1;
        *(uint2*)&Bsh[vk * PBV + vseg * 4] = rbh;
        *(uint2*)&Bsl[vk * PBV + vseg * 4] = rbl;
        __syncthreads();

        if (ks + 1 < NK) {
            int k0 = (ks + 1) * 16;
            ra0 = *(const float4*)&P[aRow + k0 + asel];
            ra1 = *(const float4*)&P[aRow + k0 + asel + 4];
            rbh = *(const uint2*)&Vh[vBase + (size_t)(k0 + vk) * Dd];
            rbl = *(const uint2*)&Vl[vBase + (size_t)(k0 + vk) * Dd];
        }

        uint32_t afh[2][4], afl[2][4];
        #pragma unroll
        for (int i = 0; i < 2; i++) {
            ldsm_x4(sAh + aoff + i * 768, afh[i][0], afh[i][1], afh[i][2], afh[i][3]);
            ldsm_x4(sAl + aoff + i * 768, afl[i][0], afl[i][1], afl[i][2], afl[i][3]);
        }
        #pragma unroll
        for (int j = 0; j < 2; j++) {
            uint32_t bh0, bh1, bh2, bh3, bl0, bl1, bl2, bl3;
            ldsm_x4_t(sBh + boff + j * 32, bh0, bh1, bh2, bh3);
            ldsm_x4_t(sBl + boff + j * 32, bl0, bl1, bl2, bl3);
            #pragma unroll
            for (int i = 0; i < 2; i++) {
                mma_bf16(c[i][2 * j], afh[i], bh0, bh1);
                mma_bf16(c[i][2 * j], afh[i], bl0, bl1);
                mma_bf16(c[i][2 * j], afl[i], bh0, bh1);
                mma_bf16(c[i][2 * j + 1], afh[i], bh2, bh3);
                mma_bf16(c[i][2 * j + 1], afh[i], bl2, bl3);
                mma_bf16(c[i][2 * j + 1], afl[i], bh2, bh3);
            }
        }
        __syncthreads();
    }

    int r = lane >> 2, cl2 = (lane & 3) * 2;
    #pragma unroll
    for (int i = 0; i < 2; i++) {
        int row = rowBase + m0 + i * 16 + r;
        #pragma unroll
        for (int j = 0; j < 4; j++) {
            int col = n0 + j * 8 + cl2;
            size_t off0 = (size_t)(b * Ll + row) * Dd + h * 64 + col;
            size_t off1 = (size_t)(b * Ll + row + 8) * Dd + h * 64 + col;
            uint32_t hh, ll;
            pack_split2(c[i][j][0], c[i][j][1], hh, ll);
            *(uint32_t*)&Oh[off0] = hh;
            *(uint32_t*)&Ol[off0] = ll;
            pack_split2(c[i][j][2], c[i][j][3], hh, ll);
            *(uint32_t*)&Oh[off1] = hh;
            *(uint32_t*)&Ol[off1] = ll;
        }
    }
}

// ---------------- launch ----------------
extern "C" void kernel_launch(void* const* d_in, const int* in_sizes, int n_in,
                              void* d_out, int out_size)
{
    const float* x   = (const float*)d_in[0];
    const float* Wq  = (const float*)d_in[1];
    const float* bq  = (const float*)d_in[2];
    const float* Wk  = (const float*)d_in[3];
    const float* bk  = (const float*)d_in[4];
    const float* Wv  = (const float*)d_in[5];
    const float* bv  = (const float*)d_in[6];
    const float* Wo  = (const float*)d_in[7];
    const float* bo  = (const float*)d_in[8];
    const float* lsc = (const float*)d_in[9];
    const float* gsc = (const float*)d_in[10];

    float* out   = (float*)d_out;
    float* attnL = out + (size_t)MLEN * Dd;
    float* attnG = attnL + (size_t)Bb * LH * Ll * Ll;

    uint16_t *xh, *xl, *Wqh, *Wql, *Wkh, *Wkl, *Wvh, *Wvl, *Woh, *Wol;
    uint16_t *Qh, *Ql, *Kh, *Kl, *Vh, *Vl, *Ohp, *Olp;
    cudaGetSymbolAddress((void**)&xh, g_xh);   cudaGetSymbolAddress((void**)&xl, g_xl);
    cudaGetSymbolAddress((void**)&Wqh, g_Wqh); cudaGetSymbolAddress((void**)&Wql, g_Wql);
    cudaGetSymbolAddress((void**)&Wkh, g_Wkh); cudaGetSymbolAddress((void**)&Wkl, g_Wkl);
    cudaGetSymbolAddress((void**)&Wvh, g_Wvh); cudaGetSymbolAddress((void**)&Wvl, g_Wvl);
    cudaGetSymbolAddress((void**)&Woh, g_Woh); cudaGetSymbolAddress((void**)&Wol, g_Wol);
    cudaGetSymbolAddress((void**)&Qh, g_Qh);   cudaGetSymbolAddress((void**)&Ql, g_Ql);
    cudaGetSymbolAddress((void**)&Kh, g_Kh);   cudaGetSymbolAddress((void**)&Kl, g_Kl);
    cudaGetSymbolAddress((void**)&Vh, g_Vh);   cudaGetSymbolAddress((void**)&Vl, g_Vl);
    cudaGetSymbolAddress((void**)&Ohp, g_Oh);  cudaGetSymbolAddress((void**)&Olp, g_Ol);

    int nx4 = MLEN * Dd / 4;      // 1048576
    int nw4 = Dd * Dd / 4;        // 262144
    split_kernel<<<nx4 / 256, 256>>>((const float4*)x, (uint2*)xh, (uint2*)xl, nx4);
    split_kernel<<<nw4 / 256, 256>>>((const float4*)Wq, (uint2*)Wqh, (uint2*)Wql, nw4);
    split_kernel<<<nw4 / 256, 256>>>((const float4*)Wk, (uint2*)Wkh, (uint2*)Wkl, nw4);
    split_kernel<<<nw4 / 256, 256>>>((const float4*)Wv, (uint2*)Wvh, (uint2*)Wvl, nw4);
    split_kernel<<<nw4 / 256, 256>>>((const float4*)Wo, (uint2*)Woh, (uint2*)Wol, nw4);

    dim3 pg(4, 32);
    gemm_proj<<<pg, 256>>>(xh, xl, Wqh, Wql, bq, Qh, Ql, nullptr, 1);
    gemm_proj<<<pg, 256>>>(xh, xl, Wkh, Wkl, bk, Kh, Kl, nullptr, 1);
    gemm_proj<<<pg, 256>>>(xh, xl, Wvh, Wvl, bv, Vh, Vl, nullptr, 1);

    scores_mma<<<dim3(8, 16, 32), 256>>>(Qh, Ql, Kh, Kl, lsc, gsc, attnL, attnG);
    softmax_kernel<<<dim3(Ll, 32), 256>>>(attnL, attnG);
    av_mma<<<dim3(16, 32), 256>>>(attnL, attnG, Vh, Vl, Ohp, Olp);

    gemm_proj<<<pg, 256>>>(Ohp, Olp, Woh, Wol, bo, nullptr, nullptr, out, 0);
}